// round 1
// baseline (speedup 1.0000x reference)
#include <cuda_runtime.h>

// ---------------------------------------------------------------------------
// Shapes (fixed by the problem)
// ---------------------------------------------------------------------------
namespace {
constexpr int BN   = 64;    // batch
constexpr int HWIN = 240;   // input spatial
constexpr int H1   = 120;   // after stem (s2)
constexpr int H2   = 60;    // after conv1 (s2)
constexpr int C0   = 3;
constexpr int C1   = 32;
constexpr int C2   = 64;
constexpr int C3   = 128;
constexpr int HEADN = 1280;
constexpr int P3     = 40;                 // pixels per conv3 chunk
constexpr int NCHUNK = (H2 * H2) / P3;     // 90
}

// ---------------------------------------------------------------------------
// Scratch (no allocations allowed -> __device__ globals)
// ---------------------------------------------------------------------------
__device__ float g_h1[(size_t)BN * C1 * H1 * H1];   // 118 MB
__device__ float g_h2[(size_t)BN * C2 * H2 * H2];   //  59 MB
__device__ float g_part[BN * NCHUNK * C3];          // per-chunk GAP partials
__device__ float g_gap[BN * C3];
__device__ float g_wst[27 * C1];                    // stem weights, [kk][co]
__device__ float g_w1t[288 * C2];                   // conv2 weights, [kk][co]

// ---------------------------------------------------------------------------
// Weight transpose: [co][ci*9+k] -> [ci*9+k][co] so conv inner loops read
// consecutive shared floats (LDS.128) instead of strided broadcasts.
// ---------------------------------------------------------------------------
__global__ void prep_kernel(const float* __restrict__ wstem,
                            const float* __restrict__ w1) {
    int i = blockIdx.x * blockDim.x + threadIdx.x;
    if (i < 27 * C1) {
        int co = i / 27, kk = i % 27;
        g_wst[kk * C1 + co] = wstem[i];
    }
    if (i < 288 * C2) {
        int co = i / 288, kk = i % 288;
        g_w1t[kk * C2 + co] = w1[i];
    }
}

// ---------------------------------------------------------------------------
// Conv1 (stem): 3 -> 32, 3x3 stride 2 pad 1, 240^2 -> 120^2, BN-fold + ReLU.
// One thread per output pixel, all 32 output channels in registers.
// ---------------------------------------------------------------------------
__global__ void conv1_kernel(const float* __restrict__ x,
                             const float* __restrict__ a,
                             const float* __restrict__ b) {
    __shared__ float ws[27 * C1];   // [kk][co]
    __shared__ float as[C1], bs[C1];
    for (int i = threadIdx.x; i < 27 * C1; i += blockDim.x) ws[i] = g_wst[i];
    if (threadIdx.x < C1) {
        as[threadIdx.x] = a[threadIdx.x];
        bs[threadIdx.x] = b[threadIdx.x];
    }
    __syncthreads();

    int idx = blockIdx.x * blockDim.x + threadIdx.x;   // grid sized exactly
    int ox = idx % H1;
    int oy = (idx / H1) % H1;
    int n  = idx / (H1 * H1);

    float acc[C1];
#pragma unroll
    for (int co = 0; co < C1; co++) acc[co] = 0.f;

    const float* xn = x + (size_t)n * C0 * HWIN * HWIN;
#pragma unroll
    for (int ky = 0; ky < 3; ky++) {
        int iy = oy * 2 - 1 + ky;
        if (iy < 0 || iy >= HWIN) continue;
#pragma unroll
        for (int kx = 0; kx < 3; kx++) {
            int ix = ox * 2 - 1 + kx;
            if (ix < 0 || ix >= HWIN) continue;
#pragma unroll
            for (int ci = 0; ci < C0; ci++) {
                float v = __ldg(&xn[ci * HWIN * HWIN + iy * HWIN + ix]);
                const float* wp = &ws[(ci * 9 + ky * 3 + kx) * C1];
#pragma unroll
                for (int co = 0; co < C1; co++) acc[co] += v * wp[co];
            }
        }
    }

    float* outp = g_h1 + (size_t)n * C1 * H1 * H1 + oy * H1 + ox;
#pragma unroll
    for (int co = 0; co < C1; co++) {
        float y = acc[co] * as[co] + bs[co];
        outp[(size_t)co * H1 * H1] = fmaxf(y, 0.f);
    }
}

// ---------------------------------------------------------------------------
// Conv2: 32 -> 64, 3x3 stride 2 pad 1, 120^2 -> 60^2, BN-fold + ReLU.
// blockIdx.y selects 32-channel half; one thread per output pixel,
// 32 output channels in registers. Weights staged in shared [kk][j].
// ---------------------------------------------------------------------------
__global__ void conv2_kernel(const float* __restrict__ a,
                             const float* __restrict__ b) {
    __shared__ float ws[288 * 32];   // 36.9 KB: [ci*9+k][j]
    __shared__ float as[32], bs[32];
    int half = blockIdx.y;
    for (int i = threadIdx.x; i < 288 * 32; i += blockDim.x) {
        int kk = i >> 5, j = i & 31;
        ws[i] = g_w1t[kk * C2 + half * 32 + j];   // coalesced 32-float runs
    }
    if (threadIdx.x < 32) {
        as[threadIdx.x] = a[half * 32 + threadIdx.x];
        bs[threadIdx.x] = b[half * 32 + threadIdx.x];
    }
    __syncthreads();

    int idx = blockIdx.x * blockDim.x + threadIdx.x;   // grid sized exactly
    int ox = idx % H2;
    int oy = (idx / H2) % H2;
    int n  = idx / (H2 * H2);

    float acc[32];
#pragma unroll
    for (int j = 0; j < 32; j++) acc[j] = 0.f;

    const float* hin = g_h1 + (size_t)n * C1 * H1 * H1;
    for (int ci = 0; ci < C1; ci++) {
        const float* hc = hin + (size_t)ci * H1 * H1;
        const float* wc = ws + ci * 9 * 32;
#pragma unroll
        for (int ky = 0; ky < 3; ky++) {
            int iy = oy * 2 - 1 + ky;
            if (iy < 0 || iy >= H1) continue;
#pragma unroll
            for (int kx = 0; kx < 3; kx++) {
                int ix = ox * 2 - 1 + kx;
                if (ix < 0 || ix >= H1) continue;
                float v = __ldg(&hc[iy * H1 + ix]);
                const float* wp = wc + (ky * 3 + kx) * 32;
#pragma unroll
                for (int j = 0; j < 32; j++) acc[j] += v * wp[j];
            }
        }
    }

    float* outp = g_h2 + (size_t)n * C2 * H2 * H2 + oy * H2 + ox;
#pragma unroll
    for (int j = 0; j < 32; j++) {
        float y = acc[j] * as[j] + bs[j];
        outp[(size_t)(half * 32 + j) * H2 * H2] = fmaxf(y, 0.f);
    }
}

// ---------------------------------------------------------------------------
// Conv3 (1x1, 64->128) + BN-fold + ReLU + partial GAP, fused.
// Block = (chunk of P3 pixels, batch n). Thread c (0..127) holds w2[c,:]
// in 64 registers; h2 tile staged in shared; per-chunk partial sums written
// deterministically (no atomics).
// ---------------------------------------------------------------------------
__global__ void conv3_gap_kernel(const float* __restrict__ w2,
                                 const float* __restrict__ a2,
                                 const float* __restrict__ b2) {
    __shared__ float hs[C2 * P3];   // 10.2 KB, [k][dp]
    int n = blockIdx.y;
    int chunk = blockIdx.x;
    int p0 = chunk * P3;
    int c = threadIdx.x;            // output channel, blockDim.x == 128

    float wreg[C2];
#pragma unroll
    for (int k = 0; k < C2; k++) wreg[k] = __ldg(&w2[c * C2 + k]);
    float ac = __ldg(&a2[c]);
    float bc = __ldg(&b2[c]);

    const float* h2n = g_h2 + (size_t)n * C2 * H2 * H2;
    for (int i = threadIdx.x; i < C2 * P3; i += blockDim.x) {
        int k = i / P3, dp = i % P3;
        hs[i] = h2n[(size_t)k * (H2 * H2) + p0 + dp];
    }
    __syncthreads();

    float sum = 0.f;
    for (int dp = 0; dp < P3; dp++) {
        float dot = 0.f;
#pragma unroll
        for (int k = 0; k < C2; k++) dot += wreg[k] * hs[k * P3 + dp];
        sum += fmaxf(dot * ac + bc, 0.f);
    }
    g_part[(n * NCHUNK + chunk) * C3 + c] = sum;
}

// ---------------------------------------------------------------------------
// Reduce GAP partials -> g_gap (mean over 3600 pixels).
// ---------------------------------------------------------------------------
__global__ void gap_reduce_kernel() {
    int n = blockIdx.x, c = threadIdx.x;   // blockDim.x == 128
    float s = 0.f;
    for (int ch = 0; ch < NCHUNK; ch++) s += g_part[(n * NCHUNK + ch) * C3 + c];
    g_gap[n * C3 + c] = s * (1.f / (float)(H2 * H2));
}

// ---------------------------------------------------------------------------
// Head: out[n,o] = relu(a[o] * dot(gap[n,:], w_head[o,:]) + b[o]).
// ---------------------------------------------------------------------------
__global__ void head_kernel(const float* __restrict__ wh,
                            const float* __restrict__ ah,
                            const float* __restrict__ bh,
                            float* __restrict__ out) {
    __shared__ float gs[C3];
    int n = blockIdx.y;
    if (threadIdx.x < C3) gs[threadIdx.x] = g_gap[n * C3 + threadIdx.x];
    __syncthreads();

    int o = blockIdx.x * blockDim.x + threadIdx.x;
    if (o >= HEADN) return;

    const float* wr = wh + (size_t)o * C3;
    float dot = 0.f;
#pragma unroll 8
    for (int k = 0; k < C3; k++) dot += __ldg(&wr[k]) * gs[k];
    out[(size_t)n * HEADN + o] = fmaxf(dot * __ldg(&ah[o]) + __ldg(&bh[o]), 0.f);
}

// ---------------------------------------------------------------------------
// Launch
// ---------------------------------------------------------------------------
extern "C" void kernel_launch(void* const* d_in, const int* in_sizes, int n_in,
                              void* d_out, int out_size) {
    const float* x      = (const float*)d_in[0];
    const float* w_stem = (const float*)d_in[1];
    const float* a_stem = (const float*)d_in[2];
    const float* b_stem = (const float*)d_in[3];
    const float* w1     = (const float*)d_in[4];
    const float* a1     = (const float*)d_in[5];
    const float* b1     = (const float*)d_in[6];
    const float* w2     = (const float*)d_in[7];
    const float* a2     = (const float*)d_in[8];
    const float* b2     = (const float*)d_in[9];
    const float* w_head = (const float*)d_in[10];
    const float* a_head = (const float*)d_in[11];
    const float* b_head = (const float*)d_in[12];
    float* out = (float*)d_out;

    prep_kernel<<<(288 * C2 + 255) / 256, 256>>>(w_stem, w1);

    conv1_kernel<<<BN * H1 * H1 / 128, 128>>>(x, a_stem, b_stem);

    dim3 g2(BN * H2 * H2 / 128, 2);
    conv2_kernel<<<g2, 128>>>(a1, b1);

    dim3 g3(NCHUNK, BN);
    conv3_gap_kernel<<<g3, C3>>>(w2, a2, b2);

    gap_reduce_kernel<<<BN, C3>>>();

    head_kernel<<<dim3((HEADN + 255) / 256, BN), 256>>>(w_head, a_head, b_head, out);
}

// round 2
// speedup vs baseline: 1.3920x; 1.3920x over previous
#include <cuda_runtime.h>

// ---------------------------------------------------------------------------
// Shapes (fixed by the problem)
// ---------------------------------------------------------------------------
namespace {
constexpr int BN   = 64;    // batch
constexpr int HWIN = 240;   // input spatial
constexpr int H1   = 120;   // after stem (s2)
constexpr int H2   = 60;    // after conv1 (s2)
constexpr int C0   = 3;
constexpr int C1   = 32;
constexpr int C2   = 64;
constexpr int C3   = 128;
constexpr int HEADN = 1280;
constexpr int P3     = 60;                 // pixels per conv3 chunk (one row)
constexpr int NCHUNK = (H2 * H2) / P3;     // 60
}

// ---------------------------------------------------------------------------
// Scratch (no allocations allowed -> __device__ globals)
// ---------------------------------------------------------------------------
__device__ float g_h1[(size_t)BN * C1 * H1 * H1];   // 118 MB
__device__ float g_h2[(size_t)BN * C2 * H2 * H2];   //  59 MB
__device__ float g_part[BN * NCHUNK * C3];          // per-chunk GAP partials
__device__ float g_gap[BN * C3];
__device__ float g_wst[27 * C1];                    // stem weights, [kk][co]
__device__ float g_w1t[288 * C2];                   // conv2 weights, [kk][co]

// ---------------------------------------------------------------------------
// Weight transpose: [co][ci*9+k] -> [ci*9+k][co]
// ---------------------------------------------------------------------------
__global__ void prep_kernel(const float* __restrict__ wstem,
                            const float* __restrict__ w1) {
    int i = blockIdx.x * blockDim.x + threadIdx.x;
    if (i < 27 * C1) {
        int co = i / 27, kk = i % 27;
        g_wst[kk * C1 + co] = wstem[i];
    }
    if (i < 288 * C2) {
        int co = i / 288, kk = i % 288;
        g_w1t[kk * C2 + co] = w1[i];
    }
}

// ---------------------------------------------------------------------------
// Conv1 (stem): 3 -> 32, 3x3 s2 p1, 240^2 -> 120^2, BN-fold + ReLU.
// One thread per output pixel, 32 output channels in registers.
// ---------------------------------------------------------------------------
__global__ void conv1_kernel(const float* __restrict__ x,
                             const float* __restrict__ a,
                             const float* __restrict__ b) {
    __shared__ float ws[27 * C1];   // [kk][co]
    __shared__ float as[C1], bs[C1];
    for (int i = threadIdx.x; i < 27 * C1; i += blockDim.x) ws[i] = g_wst[i];
    if (threadIdx.x < C1) {
        as[threadIdx.x] = a[threadIdx.x];
        bs[threadIdx.x] = b[threadIdx.x];
    }
    __syncthreads();

    int idx = blockIdx.x * blockDim.x + threadIdx.x;   // grid sized exactly
    int ox = idx % H1;
    int oy = (idx / H1) % H1;
    int n  = idx / (H1 * H1);

    float acc[C1];
#pragma unroll
    for (int co = 0; co < C1; co++) acc[co] = 0.f;

    const float* xn = x + (size_t)n * C0 * HWIN * HWIN;
#pragma unroll
    for (int ky = 0; ky < 3; ky++) {
        int iy = oy * 2 - 1 + ky;
        if (iy < 0 || iy >= HWIN) continue;
#pragma unroll
        for (int kx = 0; kx < 3; kx++) {
            int ix = ox * 2 - 1 + kx;
            if (ix < 0 || ix >= HWIN) continue;
#pragma unroll
            for (int ci = 0; ci < C0; ci++) {
                float v = __ldg(&xn[ci * HWIN * HWIN + iy * HWIN + ix]);
                const float4* wp = (const float4*)&ws[(ci * 9 + ky * 3 + kx) * C1];
#pragma unroll
                for (int j4 = 0; j4 < C1 / 4; j4++) {
                    float4 w = wp[j4];
                    acc[j4 * 4 + 0] += v * w.x;
                    acc[j4 * 4 + 1] += v * w.y;
                    acc[j4 * 4 + 2] += v * w.z;
                    acc[j4 * 4 + 3] += v * w.w;
                }
            }
        }
    }

    float* outp = g_h1 + (size_t)n * C1 * H1 * H1 + oy * H1 + ox;
#pragma unroll
    for (int co = 0; co < C1; co++) {
        float y = acc[co] * as[co] + bs[co];
        outp[(size_t)co * H1 * H1] = fmaxf(y, 0.f);
    }
}

// ---------------------------------------------------------------------------
// Conv2: 32 -> 64, 3x3 s2 p1, 120^2 -> 60^2, BN-fold + ReLU.
// blockIdx.y selects 32-channel half. Each thread computes TWO adjacent
// output pixels (ox0, ox0+1) for 32 channels -> 64 FFMA per weight fetch.
// ---------------------------------------------------------------------------
__global__ void conv2_kernel(const float* __restrict__ a,
                             const float* __restrict__ b) {
    __shared__ float ws[288 * 32];   // 36.9 KB: [ci*9+k][j]
    __shared__ float as[32], bs[32];
    int half = blockIdx.y;
    for (int i = threadIdx.x; i < 288 * 32; i += blockDim.x) {
        int kk = i >> 5, j = i & 31;
        ws[i] = g_w1t[kk * C2 + half * 32 + j];
    }
    if (threadIdx.x < 32) {
        as[threadIdx.x] = a[half * 32 + threadIdx.x];
        bs[threadIdx.x] = b[half * 32 + threadIdx.x];
    }
    __syncthreads();

    int p  = blockIdx.x * blockDim.x + threadIdx.x;    // pixel-pair index
    int xp = p % (H2 / 2);
    int oy = (p / (H2 / 2)) % H2;
    int n  = p / (H2 / 2 * H2);
    int ox0 = xp * 2;

    float acc0[32], acc1[32];
#pragma unroll
    for (int j = 0; j < 32; j++) { acc0[j] = 0.f; acc1[j] = 0.f; }

    const float* hin = g_h1 + (size_t)n * C1 * H1 * H1;
    for (int ci = 0; ci < C1; ci++) {
        const float* hc = hin + (size_t)ci * H1 * H1;
#pragma unroll
        for (int ky = 0; ky < 3; ky++) {
            int iy = oy * 2 - 1 + ky;
            if ((unsigned)iy >= (unsigned)H1) continue;
            const float* hr = hc + iy * H1;
#pragma unroll
            for (int kx = 0; kx < 3; kx++) {
                int ix0 = ox0 * 2 - 1 + kx;      // ix0 in [-1, 117]
                float v0 = (ix0 >= 0) ? __ldg(&hr[ix0]) : 0.f;
                float v1 = __ldg(&hr[ix0 + 2]);  // always in [1, 119]
                const float4* wp = (const float4*)&ws[(ci * 9 + ky * 3 + kx) * 32];
#pragma unroll
                for (int j4 = 0; j4 < 8; j4++) {
                    float4 w = wp[j4];
                    acc0[j4 * 4 + 0] += v0 * w.x; acc1[j4 * 4 + 0] += v1 * w.x;
                    acc0[j4 * 4 + 1] += v0 * w.y; acc1[j4 * 4 + 1] += v1 * w.y;
                    acc0[j4 * 4 + 2] += v0 * w.z; acc1[j4 * 4 + 2] += v1 * w.z;
                    acc0[j4 * 4 + 3] += v0 * w.w; acc1[j4 * 4 + 3] += v1 * w.w;
                }
            }
        }
    }

    float* outp = g_h2 + (size_t)n * C2 * H2 * H2 + oy * H2 + ox0;
#pragma unroll
    for (int j = 0; j < 32; j++) {
        float2 y;
        y.x = fmaxf(acc0[j] * as[j] + bs[j], 0.f);
        y.y = fmaxf(acc1[j] * as[j] + bs[j], 0.f);
        *(float2*)&outp[(size_t)(half * 32 + j) * H2 * H2] = y;
    }
}

// ---------------------------------------------------------------------------
// Conv3 (1x1, 64->128) + BN-fold + ReLU + partial GAP, fused.
// Block = (row chunk of 60 pixels, batch n). Thread c holds w2[c,:] in regs.
// Inner loop: float4 LDS over 4 pixels -> 4 FFMA per LDS.128, 4 acc chains.
// ---------------------------------------------------------------------------
__global__ void conv3_gap_kernel(const float* __restrict__ w2,
                                 const float* __restrict__ a2,
                                 const float* __restrict__ b2) {
    __shared__ float hs[C2 * P3];   // 15 KB, [k][dp], 60 floats/row (16B-mult)
    int n = blockIdx.y;
    int chunk = blockIdx.x;
    int p0 = chunk * P3;
    int c = threadIdx.x;            // output channel, blockDim.x == 128

    float wreg[C2];
#pragma unroll
    for (int k = 0; k < C2; k++) wreg[k] = __ldg(&w2[c * C2 + k]);
    float ac = __ldg(&a2[c]);
    float bc = __ldg(&b2[c]);

    const float* h2n = g_h2 + (size_t)n * C2 * H2 * H2;
    for (int i = threadIdx.x; i < C2 * P3; i += blockDim.x) {
        int k = i / P3, dp = i % P3;
        hs[i] = h2n[(size_t)k * (H2 * H2) + p0 + dp];
    }
    __syncthreads();

    float sum = 0.f;
    for (int dp4 = 0; dp4 < P3 / 4; dp4++) {
        float4 d = make_float4(0.f, 0.f, 0.f, 0.f);
#pragma unroll
        for (int k = 0; k < C2; k++) {
            float4 h = *(const float4*)&hs[k * P3 + dp4 * 4];
            d.x += wreg[k] * h.x;
            d.y += wreg[k] * h.y;
            d.z += wreg[k] * h.z;
            d.w += wreg[k] * h.w;
        }
        sum += fmaxf(d.x * ac + bc, 0.f);
        sum += fmaxf(d.y * ac + bc, 0.f);
        sum += fmaxf(d.z * ac + bc, 0.f);
        sum += fmaxf(d.w * ac + bc, 0.f);
    }
    g_part[(n * NCHUNK + chunk) * C3 + c] = sum;
}

// ---------------------------------------------------------------------------
// Reduce GAP partials -> g_gap (mean over 3600 pixels).
// ---------------------------------------------------------------------------
__global__ void gap_reduce_kernel() {
    int n = blockIdx.x, c = threadIdx.x;   // blockDim.x == 128
    float s = 0.f;
    for (int ch = 0; ch < NCHUNK; ch++) s += g_part[(n * NCHUNK + ch) * C3 + c];
    g_gap[n * C3 + c] = s * (1.f / (float)(H2 * H2));
}

// ---------------------------------------------------------------------------
// Head: out[n,o] = relu(a[o] * dot(gap[n,:], w_head[o,:]) + b[o]).
// ---------------------------------------------------------------------------
__global__ void head_kernel(const float* __restrict__ wh,
                            const float* __restrict__ ah,
                            const float* __restrict__ bh,
                            float* __restrict__ out) {
    __shared__ float gs[C3];
    int n = blockIdx.y;
    if (threadIdx.x < C3) gs[threadIdx.x] = g_gap[n * C3 + threadIdx.x];
    __syncthreads();

    int o = blockIdx.x * blockDim.x + threadIdx.x;
    if (o >= HEADN) return;

    const float* wr = wh + (size_t)o * C3;
    float dot = 0.f;
#pragma unroll 8
    for (int k = 0; k < C3; k++) dot += __ldg(&wr[k]) * gs[k];
    out[(size_t)n * HEADN + o] = fmaxf(dot * __ldg(&ah[o]) + __ldg(&bh[o]), 0.f);
}

// ---------------------------------------------------------------------------
// Launch
// ---------------------------------------------------------------------------
extern "C" void kernel_launch(void* const* d_in, const int* in_sizes, int n_in,
                              void* d_out, int out_size) {
    const float* x      = (const float*)d_in[0];
    const float* w_stem = (const float*)d_in[1];
    const float* a_stem = (const float*)d_in[2];
    const float* b_stem = (const float*)d_in[3];
    const float* w1     = (const float*)d_in[4];
    const float* a1     = (const float*)d_in[5];
    const float* b1     = (const float*)d_in[6];
    const float* w2     = (const float*)d_in[7];
    const float* a2     = (const float*)d_in[8];
    const float* b2     = (const float*)d_in[9];
    const float* w_head = (const float*)d_in[10];
    const float* a_head = (const float*)d_in[11];
    const float* b_head = (const float*)d_in[12];
    float* out = (float*)d_out;

    prep_kernel<<<(288 * C2 + 255) / 256, 256>>>(w_stem, w1);

    conv1_kernel<<<BN * H1 * H1 / 128, 128>>>(x, a_stem, b_stem);

    dim3 g2(BN * H2 * (H2 / 2) / 128, 2);   // 2 pixels per thread
    conv2_kernel<<<g2, 128>>>(a1, b1);

    dim3 g3(NCHUNK, BN);
    conv3_gap_kernel<<<g3, C3>>>(w2, a2, b2);

    gap_reduce_kernel<<<BN, C3>>>();

    head_kernel<<<dim3((HEADN + 255) / 256, BN), 256>>>(w_head, a_head, b_head, out);
}

// round 3
// speedup vs baseline: 1.3926x; 1.0005x over previous
#include <cuda_runtime.h>

// ---------------------------------------------------------------------------
// Shapes
// ---------------------------------------------------------------------------
namespace {
constexpr int BN   = 64;
constexpr int HWIN = 240;
constexpr int H1   = 120;
constexpr int H2   = 60;
constexpr int C0   = 3;
constexpr int C1   = 32;
constexpr int C2   = 64;
constexpr int C3   = 128;
constexpr int HEADN = 1280;
constexpr int PIX2  = H2 * H2;          // 3600
constexpr int P3    = 64;               // conv3 px per block
constexpr int NCHUNK = (PIX2 + P3 - 1) / P3;   // 57
}

// ---------------------------------------------------------------------------
// Scratch
// ---------------------------------------------------------------------------
__device__ float g_h1[(size_t)BN * C1 * H1 * H1];
__device__ float g_h2[(size_t)BN * C2 * PIX2];
__device__ float g_part[BN * NCHUNK * C3];
__device__ float g_gap[BN * C3];
__device__ float g_wst[27 * C1];    // stem  [ci*9+tap][co]
__device__ float g_w1t[288 * C2];   // conv2 [ci*9+tap][co]
__device__ float g_w2t[C2 * C3];    // conv3 [k][co]

// ---------------------------------------------------------------------------
// Weight transposes
// ---------------------------------------------------------------------------
__global__ void prep_kernel(const float* __restrict__ wstem,
                            const float* __restrict__ w1,
                            const float* __restrict__ w2) {
    int i = blockIdx.x * blockDim.x + threadIdx.x;
    if (i < 27 * C1) {
        int co = i / 27, kk = i % 27;
        g_wst[kk * C1 + co] = wstem[i];
    }
    if (i < 288 * C2) {
        int co = i / 288, kk = i % 288;
        g_w1t[kk * C2 + co] = w1[i];
    }
    if (i < C2 * C3) {
        int k = i / C3, c = i % C3;
        g_w2t[k * C3 + c] = w2[c * C2 + k];
    }
}

// ---------------------------------------------------------------------------
// Conv1 (stem): 3->32, 3x3 s2 p1, 240^2 -> 120^2, BN + ReLU.
// Block = (oy, n). Parity-split staging; thread tile 8ch x 4px.
// threads: cg = tx%4 (4 grp x 8ch = 32ch), pg = tx/4 (32 grp x 4px, 30 valid)
// ---------------------------------------------------------------------------
__global__ __launch_bounds__(128) void conv1_kernel(
        const float* __restrict__ x,
        const float* __restrict__ a,
        const float* __restrict__ b) {
    __shared__ float sO[9][132];   // O[r][j] = in(2j-1), r = ky*3+ci
    __shared__ float sE[9][132];   // E[r][j] = in(2j)
    __shared__ float ws[27 * C1];  // [ci*9+tap][co]
    __shared__ float as[C1], bs[C1];

    int oy = blockIdx.x, n = blockIdx.y;
    int tx = threadIdx.x;

    for (int i = tx; i < 27 * C1; i += 128) ws[i] = g_wst[i];
    if (tx < C1) { as[tx] = a[tx]; bs[tx] = b[tx]; }

    const float* xn = x + (size_t)n * C0 * HWIN * HWIN;
    for (int t = tx; t < 2 * 9 * 132; t += 128) {
        int half = t / (9 * 132);
        int rem  = t % (9 * 132);
        int r = rem / 132, j = rem % 132;
        int ky = r / 3, ci = r % 3;
        int iy = oy * 2 - 1 + ky;
        const float* row = xn + ci * HWIN * HWIN + iy * HWIN;
        float v = 0.f;
        if (iy >= 0) {
            if (half == 0) {              // O
                int sx = 2 * j - 1;
                if (j <= 120 && sx >= 0) v = row[sx];
            } else {                      // E
                if (j <= 119) v = row[2 * j];
            }
        }
        if (half == 0) sO[r][j] = v; else sE[r][j] = v;
    }
    __syncthreads();

    int cg = tx & 3, pg = tx >> 2;
    int c0 = cg * 8, ox0 = pg * 4;

    float acc[8][4];
#pragma unroll
    for (int i = 0; i < 8; i++)
#pragma unroll
        for (int j = 0; j < 4; j++) acc[i][j] = 0.f;

#pragma unroll
    for (int ky = 0; ky < 3; ky++) {
#pragma unroll
        for (int ci = 0; ci < 3; ci++) {
            int r = ky * 3 + ci;
            float4 o = *(const float4*)&sO[r][ox0];
            float  o4 = sO[r][ox0 + 4];
            float4 e = *(const float4*)&sE[r][ox0];
#pragma unroll
            for (int kx = 0; kx < 3; kx++) {
                float v0, v1, v2, v3;
                if (kx == 0)      { v0 = o.x; v1 = o.y; v2 = o.z; v3 = o.w; }
                else if (kx == 1) { v0 = e.x; v1 = e.y; v2 = e.z; v3 = e.w; }
                else              { v0 = o.y; v1 = o.z; v2 = o.w; v3 = o4;  }
                const float* wp = &ws[(ci * 9 + ky * 3 + kx) * C1 + c0];
                float4 wa = *(const float4*)wp;
                float4 wb = *(const float4*)(wp + 4);
                float w8[8] = {wa.x, wa.y, wa.z, wa.w, wb.x, wb.y, wb.z, wb.w};
#pragma unroll
                for (int i = 0; i < 8; i++) {
                    acc[i][0] += w8[i] * v0;
                    acc[i][1] += w8[i] * v1;
                    acc[i][2] += w8[i] * v2;
                    acc[i][3] += w8[i] * v3;
                }
            }
        }
    }

    if (pg < 30) {
        float* outp = g_h1 + (size_t)n * C1 * H1 * H1 + oy * H1 + ox0;
#pragma unroll
        for (int i = 0; i < 8; i++) {
            float ai = as[c0 + i], bi = bs[c0 + i];
            float4 y;
            y.x = fmaxf(acc[i][0] * ai + bi, 0.f);
            y.y = fmaxf(acc[i][1] * ai + bi, 0.f);
            y.z = fmaxf(acc[i][2] * ai + bi, 0.f);
            y.w = fmaxf(acc[i][3] * ai + bi, 0.f);
            *(float4*)&outp[(size_t)(c0 + i) * H1 * H1] = y;
        }
    }
}

// ---------------------------------------------------------------------------
// Conv2: 32->64, 3x3 s2 p1, 120^2 -> 60^2, BN + ReLU.
// Block = (oy, n). 4 chunks of 8 in-channels, parity-split staging.
// threads: cg = tx%8 (8 grp x 8ch = 64ch), pg = tx/8 (16 grp x 4px, 15 valid)
// ---------------------------------------------------------------------------
__global__ __launch_bounds__(128) void conv2_kernel(
        const float* __restrict__ a,
        const float* __restrict__ b) {
    __shared__ float sO[8][3][64];      // O[i][r][j] = in(2j-1), j<=60
    __shared__ float sE[8][3][64];      // E[i][r][j] = in(2j),  j<=59
    __shared__ float wc[72 * C2];       // weights for 8 in-ch chunk
    __shared__ float as[C2], bs[C2];

    int oy = blockIdx.x, n = blockIdx.y;
    int tx = threadIdx.x;
    if (tx < C2) { as[tx] = a[tx]; bs[tx] = b[tx]; }

    int cg = tx & 7, pg = tx >> 3;
    int c0 = cg * 8, ox0 = pg * 4;

    float acc[8][4];
#pragma unroll
    for (int i = 0; i < 8; i++)
#pragma unroll
        for (int j = 0; j < 4; j++) acc[i][j] = 0.f;

    const float* hin = g_h1 + (size_t)n * C1 * H1 * H1;

    for (int c8 = 0; c8 < C1; c8 += 8) {
        __syncthreads();
        // stage weights: contiguous 72*64 floats
        const float* wsrc = g_w1t + (size_t)c8 * 9 * C2;
        for (int i4 = tx; i4 < 72 * C2 / 4; i4 += 128)
            ((float4*)wc)[i4] = ((const float4*)wsrc)[i4];
        // stage parity-split input rows
        for (int t = tx; t < 2 * 8 * 3 * 64; t += 128) {
            int half = t / (8 * 3 * 64);
            int rem  = t % (8 * 3 * 64);
            int j = rem & 63;
            int rr = rem >> 6;          // 0..23
            int i = rr / 3, r = rr % 3;
            int iy = oy * 2 - 1 + r;
            float v = 0.f;
            if (iy >= 0 && iy < H1) {
                const float* row = hin + (size_t)(c8 + i) * H1 * H1 + iy * H1;
                if (half == 0) {
                    int sx = 2 * j - 1;
                    if (j <= 60 && sx >= 0) v = row[sx];
                } else {
                    if (j <= 59) v = row[2 * j];
                }
            }
            if (half == 0) sO[i][r][j] = v; else sE[i][r][j] = v;
        }
        __syncthreads();

#pragma unroll
        for (int i = 0; i < 8; i++) {
#pragma unroll
            for (int r = 0; r < 3; r++) {
                float4 o = *(const float4*)&sO[i][r][ox0];
                float  o4 = sO[i][r][ox0 + 4];
                float4 e = *(const float4*)&sE[i][r][ox0];
#pragma unroll
                for (int kx = 0; kx < 3; kx++) {
                    float v0, v1, v2, v3;
                    if (kx == 0)      { v0 = o.x; v1 = o.y; v2 = o.z; v3 = o.w; }
                    else if (kx == 1) { v0 = e.x; v1 = e.y; v2 = e.z; v3 = e.w; }
                    else              { v0 = o.y; v1 = o.z; v2 = o.w; v3 = o4;  }
                    const float* wp = &wc[(i * 9 + r * 3 + kx) * C2 + c0];
                    float4 wa = *(const float4*)wp;
                    float4 wb = *(const float4*)(wp + 4);
                    float w8[8] = {wa.x, wa.y, wa.z, wa.w, wb.x, wb.y, wb.z, wb.w};
#pragma unroll
                    for (int q = 0; q < 8; q++) {
                        acc[q][0] += w8[q] * v0;
                        acc[q][1] += w8[q] * v1;
                        acc[q][2] += w8[q] * v2;
                        acc[q][3] += w8[q] * v3;
                    }
                }
            }
        }
    }

    if (pg < 15) {
        float* outp = g_h2 + (size_t)n * C2 * PIX2 + oy * H2 + ox0;
#pragma unroll
        for (int i = 0; i < 8; i++) {
            float ai = as[c0 + i], bi = bs[c0 + i];
            float4 y;
            y.x = fmaxf(acc[i][0] * ai + bi, 0.f);
            y.y = fmaxf(acc[i][1] * ai + bi, 0.f);
            y.z = fmaxf(acc[i][2] * ai + bi, 0.f);
            y.w = fmaxf(acc[i][3] * ai + bi, 0.f);
            *(float4*)&outp[(size_t)(c0 + i) * PIX2] = y;
        }
    }
}

// ---------------------------------------------------------------------------
// Conv3 (1x1, 64->128) + BN + ReLU + partial GAP.
// Block = (chunk of 64 px, n). Block tile 128ch x 64px, thread tile 8x8.
// threads: cg = tx%16 (16 grp x 8ch = 128ch), pg = tx/16 (8 grp x 8px)
// ---------------------------------------------------------------------------
__global__ __launch_bounds__(128) void conv3_gap_kernel(
        const float* __restrict__ a2,
        const float* __restrict__ b2) {
    __shared__ float s3[12288];          // 48 KB exactly
    float* ws = s3;                      // [k][128]   8192 floats
    float* hs = s3 + 8192;               // [k][64]    4096 floats

    int chunk = blockIdx.x, n = blockIdx.y;
    int tx = threadIdx.x;
    int P0 = chunk * P3;

    // stage weights (contiguous)
    for (int i4 = tx; i4 < 8192 / 4; i4 += 128)
        ((float4*)ws)[i4] = ((const float4*)g_w2t)[i4];

    // stage h2 tile [64k][64px]
    const float* h2n = g_h2 + (size_t)n * C2 * PIX2;
    if (chunk != NCHUNK - 1) {
        for (int i4 = tx; i4 < 4096 / 4; i4 += 128) {
            int k = i4 >> 4, p4 = i4 & 15;
            ((float4*)hs)[i4] =
                *(const float4*)&h2n[(size_t)k * PIX2 + P0 + p4 * 4];
        }
    } else {
        for (int i4 = tx; i4 < 4096 / 4; i4 += 128) {
            int k = i4 >> 4, p4 = i4 & 15;
            float4 v = make_float4(0.f, 0.f, 0.f, 0.f);
            if (P0 + p4 * 4 + 3 < PIX2)
                v = *(const float4*)&h2n[(size_t)k * PIX2 + P0 + p4 * 4];
            ((float4*)hs)[i4] = v;
        }
    }
    __syncthreads();

    int cg = tx & 15, pg = tx >> 4;
    int c0 = cg * 8, p0 = pg * 8;

    float acc[8][8];
#pragma unroll
    for (int i = 0; i < 8; i++)
#pragma unroll
        for (int j = 0; j < 8; j++) acc[i][j] = 0.f;

#pragma unroll 4
    for (int k = 0; k < C2; k++) {
        float4 ha = *(const float4*)&hs[k * 64 + p0];
        float4 hb = *(const float4*)&hs[k * 64 + p0 + 4];
        float h8[8] = {ha.x, ha.y, ha.z, ha.w, hb.x, hb.y, hb.z, hb.w};
        float4 wa = *(const float4*)&ws[k * C3 + c0];
        float4 wb = *(const float4*)&ws[k * C3 + c0 + 4];
        float w8[8] = {wa.x, wa.y, wa.z, wa.w, wb.x, wb.y, wb.z, wb.w};
#pragma unroll
        for (int i = 0; i < 8; i++)
#pragma unroll
            for (int j = 0; j < 8; j++)
                acc[i][j] += w8[i] * h8[j];
    }

    __syncthreads();                 // done reading hs; reuse it as red[]
    float* red = hs;                 // [128][8]

    bool full = (P0 + 64 <= PIX2);
#pragma unroll
    for (int i = 0; i < 8; i++) {
        float ai = __ldg(&a2[c0 + i]);
        float bi = __ldg(&b2[c0 + i]);
        float s = 0.f;
#pragma unroll
        for (int j = 0; j < 8; j++) {
            float y = fmaxf(acc[i][j] * ai + bi, 0.f);
            if (full || (P0 + p0 + j) < PIX2) s += y;
        }
        red[tx * 8 + i] = s;
    }
    __syncthreads();

    // thread t sums channel t over the 8 pixel groups
    int c = tx;
    int cgr = c >> 3, ii = c & 7;
    float tot = 0.f;
#pragma unroll
    for (int p = 0; p < 8; p++) tot += red[(p * 16 + cgr) * 8 + ii];
    g_part[((size_t)n * NCHUNK + chunk) * C3 + c] = tot;
}

// ---------------------------------------------------------------------------
// GAP reduce
// ---------------------------------------------------------------------------
__global__ void gap_reduce_kernel() {
    int n = blockIdx.x, c = threadIdx.x;
    float s = 0.f;
    for (int ch = 0; ch < NCHUNK; ch++)
        s += g_part[((size_t)n * NCHUNK + ch) * C3 + c];
    g_gap[n * C3 + c] = s * (1.f / (float)PIX2);
}

// ---------------------------------------------------------------------------
// Head GEMV
// ---------------------------------------------------------------------------
__global__ void head_kernel(const float* __restrict__ wh,
                            const float* __restrict__ ah,
                            const float* __restrict__ bh,
                            float* __restrict__ out) {
    __shared__ float gs[C3];
    int n = blockIdx.y;
    if (threadIdx.x < C3) gs[threadIdx.x] = g_gap[n * C3 + threadIdx.x];
    __syncthreads();

    int o = blockIdx.x * blockDim.x + threadIdx.x;
    if (o >= HEADN) return;

    const float* wr = wh + (size_t)o * C3;
    float dot = 0.f;
#pragma unroll 8
    for (int k = 0; k < C3; k++) dot += __ldg(&wr[k]) * gs[k];
    out[(size_t)n * HEADN + o] = fmaxf(dot * __ldg(&ah[o]) + __ldg(&bh[o]), 0.f);
}

// ---------------------------------------------------------------------------
// Launch
// ---------------------------------------------------------------------------
extern "C" void kernel_launch(void* const* d_in, const int* in_sizes, int n_in,
                              void* d_out, int out_size) {
    const float* x      = (const float*)d_in[0];
    const float* w_stem = (const float*)d_in[1];
    const float* a_stem = (const float*)d_in[2];
    const float* b_stem = (const float*)d_in[3];
    const float* w1     = (const float*)d_in[4];
    const float* a1     = (const float*)d_in[5];
    const float* b1     = (const float*)d_in[6];
    const float* w2     = (const float*)d_in[7];
    const float* a2     = (const float*)d_in[8];
    const float* b2     = (const float*)d_in[9];
    const float* w_head = (const float*)d_in[10];
    const float* a_head = (const float*)d_in[11];
    const float* b_head = (const float*)d_in[12];
    float* out = (float*)d_out;

    prep_kernel<<<(288 * C2 + 255) / 256, 256>>>(w_stem, w1, w2);

    conv1_kernel<<<dim3(H1, BN), 128>>>(x, a_stem, b_stem);

    conv2_kernel<<<dim3(H2, BN), 128>>>(a1, b1);

    conv3_gap_kernel<<<dim3(NCHUNK, BN), 128>>>(a2, b2);

    gap_reduce_kernel<<<BN, C3>>>();

    head_kernel<<<dim3((HEADN + 255) / 256, BN), 256>>>(w_head, a_head, b_head, out);
}

// round 4
// speedup vs baseline: 1.3934x; 1.0005x over previous
#include <cuda_runtime.h>

// ---------------------------------------------------------------------------
// Shapes
// ---------------------------------------------------------------------------
namespace {
constexpr int BN   = 64;
constexpr int HWIN = 240;
constexpr int H1   = 120;
constexpr int H2   = 60;
constexpr int C0   = 3;
constexpr int C1   = 32;
constexpr int C2   = 64;
constexpr int C3   = 128;
constexpr int HEADN = 1280;
constexpr int PIX2  = H2 * H2;          // 3600
constexpr int P3    = 64;               // conv3 px per block
constexpr int NCHUNK = (PIX2 + P3 - 1) / P3;   // 57
}

// ---------------------------------------------------------------------------
// Scratch
// ---------------------------------------------------------------------------
__device__ float g_h1[(size_t)BN * C1 * H1 * H1];
__device__ float g_h2[(size_t)BN * C2 * PIX2];
__device__ float g_part[BN * NCHUNK * C3];
__device__ float g_gap[BN * C3];
__device__ float g_wst[27 * C1];    // stem  [ci*9+tap][co]
__device__ float g_w1t[288 * C2];   // conv2 [ci*9+tap][co]
__device__ float g_w2t[C2 * C3];    // conv3 [k][co]

// ---------------------------------------------------------------------------
// Weight transposes
// ---------------------------------------------------------------------------
__global__ void prep_kernel(const float* __restrict__ wstem,
                            const float* __restrict__ w1,
                            const float* __restrict__ w2) {
    int i = blockIdx.x * blockDim.x + threadIdx.x;
    if (i < 27 * C1) {
        int co = i / 27, kk = i % 27;
        g_wst[kk * C1 + co] = wstem[i];
    }
    if (i < 288 * C2) {
        int co = i / 288, kk = i % 288;
        g_w1t[kk * C2 + co] = w1[i];
    }
    if (i < C2 * C3) {
        int k = i / C3, c = i % C3;
        g_w2t[k * C3 + c] = w2[c * C2 + k];
    }
}

// ---------------------------------------------------------------------------
// Conv1 (stem): 3->32, 3x3 s2 p1, 240^2 -> 120^2, BN + ReLU.
// Block = (oy, n). Parity-split staging; thread tile 8ch x 4px.
// threads: cg = tx%4 (4 grp x 8ch = 32ch), pg = tx/4 (32 grp x 4px, 30 valid)
// ---------------------------------------------------------------------------
__global__ __launch_bounds__(128) void conv1_kernel(
        const float* __restrict__ x,
        const float* __restrict__ a,
        const float* __restrict__ b) {
    __shared__ float sO[9][132];   // O[r][j] = in(2j-1), r = ky*3+ci
    __shared__ float sE[9][132];   // E[r][j] = in(2j)
    __shared__ float ws[27 * C1];  // [ci*9+tap][co]
    __shared__ float as[C1], bs[C1];

    int oy = blockIdx.x, n = blockIdx.y;
    int tx = threadIdx.x;

    for (int i = tx; i < 27 * C1; i += 128) ws[i] = g_wst[i];
    if (tx < C1) { as[tx] = a[tx]; bs[tx] = b[tx]; }

    const float* xn = x + (size_t)n * C0 * HWIN * HWIN;
    for (int t = tx; t < 2 * 9 * 132; t += 128) {
        int half = t / (9 * 132);
        int rem  = t % (9 * 132);
        int r = rem / 132, j = rem % 132;
        int ky = r / 3, ci = r % 3;
        int iy = oy * 2 - 1 + ky;
        const float* row = xn + ci * HWIN * HWIN + iy * HWIN;
        float v = 0.f;
        if (iy >= 0) {
            if (half == 0) {              // O
                int sx = 2 * j - 1;
                if (j <= 120 && sx >= 0) v = row[sx];
            } else {                      // E
                if (j <= 119) v = row[2 * j];
            }
        }
        if (half == 0) sO[r][j] = v; else sE[r][j] = v;
    }
    __syncthreads();

    int cg = tx & 3, pg = tx >> 2;
    int c0 = cg * 8, ox0 = pg * 4;

    float acc[8][4];
#pragma unroll
    for (int i = 0; i < 8; i++)
#pragma unroll
        for (int j = 0; j < 4; j++) acc[i][j] = 0.f;

#pragma unroll
    for (int ky = 0; ky < 3; ky++) {
#pragma unroll
        for (int ci = 0; ci < 3; ci++) {
            int r = ky * 3 + ci;
            float4 o = *(const float4*)&sO[r][ox0];
            float  o4 = sO[r][ox0 + 4];
            float4 e = *(const float4*)&sE[r][ox0];
#pragma unroll
            for (int kx = 0; kx < 3; kx++) {
                float v0, v1, v2, v3;
                if (kx == 0)      { v0 = o.x; v1 = o.y; v2 = o.z; v3 = o.w; }
                else if (kx == 1) { v0 = e.x; v1 = e.y; v2 = e.z; v3 = e.w; }
                else              { v0 = o.y; v1 = o.z; v2 = o.w; v3 = o4;  }
                const float* wp = &ws[(ci * 9 + ky * 3 + kx) * C1 + c0];
                float4 wa = *(const float4*)wp;
                float4 wb = *(const float4*)(wp + 4);
                float w8[8] = {wa.x, wa.y, wa.z, wa.w, wb.x, wb.y, wb.z, wb.w};
#pragma unroll
                for (int i = 0; i < 8; i++) {
                    acc[i][0] += w8[i] * v0;
                    acc[i][1] += w8[i] * v1;
                    acc[i][2] += w8[i] * v2;
                    acc[i][3] += w8[i] * v3;
                }
            }
        }
    }

    if (pg < 30) {
        float* outp = g_h1 + (size_t)n * C1 * H1 * H1 + oy * H1 + ox0;
#pragma unroll
        for (int i = 0; i < 8; i++) {
            float ai = as[c0 + i], bi = bs[c0 + i];
            float4 y;
            y.x = fmaxf(acc[i][0] * ai + bi, 0.f);
            y.y = fmaxf(acc[i][1] * ai + bi, 0.f);
            y.z = fmaxf(acc[i][2] * ai + bi, 0.f);
            y.w = fmaxf(acc[i][3] * ai + bi, 0.f);
            *(float4*)&outp[(size_t)(c0 + i) * H1 * H1] = y;
        }
    }
}

// ---------------------------------------------------------------------------
// Conv2: 32->64, 3x3 s2 p1, 120^2 -> 60^2, BN + ReLU.
// Block = (oy, n). 4 chunks of 8 in-channels, parity-split staging.
// threads: cg = tx%8 (8 grp x 8ch = 64ch), pg = tx/8 (16 grp x 4px, 15 valid)
// ---------------------------------------------------------------------------
__global__ __launch_bounds__(128) void conv2_kernel(
        const float* __restrict__ a,
        const float* __restrict__ b) {
    __shared__ float sO[8][3][64];      // O[i][r][j] = in(2j-1), j<=60
    __shared__ float sE[8][3][64];      // E[i][r][j] = in(2j),  j<=59
    __shared__ float wc[72 * C2];       // weights for 8 in-ch chunk
    __shared__ float as[C2], bs[C2];

    int oy = blockIdx.x, n = blockIdx.y;
    int tx = threadIdx.x;
    if (tx < C2) { as[tx] = a[tx]; bs[tx] = b[tx]; }

    int cg = tx & 7, pg = tx >> 3;
    int c0 = cg * 8, ox0 = pg * 4;

    float acc[8][4];
#pragma unroll
    for (int i = 0; i < 8; i++)
#pragma unroll
        for (int j = 0; j < 4; j++) acc[i][j] = 0.f;

    const float* hin = g_h1 + (size_t)n * C1 * H1 * H1;

    for (int c8 = 0; c8 < C1; c8 += 8) {
        __syncthreads();
        // stage weights: contiguous 72*64 floats
        const float* wsrc = g_w1t + (size_t)c8 * 9 * C2;
        for (int i4 = tx; i4 < 72 * C2 / 4; i4 += 128)
            ((float4*)wc)[i4] = ((const float4*)wsrc)[i4];
        // stage parity-split input rows
        for (int t = tx; t < 2 * 8 * 3 * 64; t += 128) {
            int half = t / (8 * 3 * 64);
            int rem  = t % (8 * 3 * 64);
            int j = rem & 63;
            int rr = rem >> 6;          // 0..23
            int i = rr / 3, r = rr % 3;
            int iy = oy * 2 - 1 + r;
            float v = 0.f;
            if (iy >= 0 && iy < H1) {
                const float* row = hin + (size_t)(c8 + i) * H1 * H1 + iy * H1;
                if (half == 0) {
                    int sx = 2 * j - 1;
                    if (j <= 60 && sx >= 0) v = row[sx];
                } else {
                    if (j <= 59) v = row[2 * j];
                }
            }
            if (half == 0) sO[i][r][j] = v; else sE[i][r][j] = v;
        }
        __syncthreads();

#pragma unroll
        for (int i = 0; i < 8; i++) {
#pragma unroll
            for (int r = 0; r < 3; r++) {
                float4 o = *(const float4*)&sO[i][r][ox0];
                float  o4 = sO[i][r][ox0 + 4];
                float4 e = *(const float4*)&sE[i][r][ox0];
#pragma unroll
                for (int kx = 0; kx < 3; kx++) {
                    float v0, v1, v2, v3;
                    if (kx == 0)      { v0 = o.x; v1 = o.y; v2 = o.z; v3 = o.w; }
                    else if (kx == 1) { v0 = e.x; v1 = e.y; v2 = e.z; v3 = e.w; }
                    else              { v0 = o.y; v1 = o.z; v2 = o.w; v3 = o4;  }
                    const float* wp = &wc[(i * 9 + r * 3 + kx) * C2 + c0];
                    float4 wa = *(const float4*)wp;
                    float4 wb = *(const float4*)(wp + 4);
                    float w8[8] = {wa.x, wa.y, wa.z, wa.w, wb.x, wb.y, wb.z, wb.w};
#pragma unroll
                    for (int q = 0; q < 8; q++) {
                        acc[q][0] += w8[q] * v0;
                        acc[q][1] += w8[q] * v1;
                        acc[q][2] += w8[q] * v2;
                        acc[q][3] += w8[q] * v3;
                    }
                }
            }
        }
    }

    if (pg < 15) {
        float* outp = g_h2 + (size_t)n * C2 * PIX2 + oy * H2 + ox0;
#pragma unroll
        for (int i = 0; i < 8; i++) {
            float ai = as[c0 + i], bi = bs[c0 + i];
            float4 y;
            y.x = fmaxf(acc[i][0] * ai + bi, 0.f);
            y.y = fmaxf(acc[i][1] * ai + bi, 0.f);
            y.z = fmaxf(acc[i][2] * ai + bi, 0.f);
            y.w = fmaxf(acc[i][3] * ai + bi, 0.f);
            *(float4*)&outp[(size_t)(c0 + i) * PIX2] = y;
        }
    }
}

// ---------------------------------------------------------------------------
// Conv3 (1x1, 64->128) + BN + ReLU + partial GAP.
// Block = (chunk of 64 px, n). Block tile 128ch x 64px, thread tile 8x8.
// threads: cg = tx%16 (16 grp x 8ch = 128ch), pg = tx/16 (8 grp x 8px)
// ---------------------------------------------------------------------------
__global__ __launch_bounds__(128) void conv3_gap_kernel(
        const float* __restrict__ a2,
        const float* __restrict__ b2) {
    __shared__ float s3[12288];          // 48 KB exactly
    float* ws = s3;                      // [k][128]   8192 floats
    float* hs = s3 + 8192;               // [k][64]    4096 floats

    int chunk = blockIdx.x, n = blockIdx.y;
    int tx = threadIdx.x;
    int P0 = chunk * P3;

    // stage weights (contiguous)
    for (int i4 = tx; i4 < 8192 / 4; i4 += 128)
        ((float4*)ws)[i4] = ((const float4*)g_w2t)[i4];

    // stage h2 tile [64k][64px]
    const float* h2n = g_h2 + (size_t)n * C2 * PIX2;
    if (chunk != NCHUNK - 1) {
        for (int i4 = tx; i4 < 4096 / 4; i4 += 128) {
            int k = i4 >> 4, p4 = i4 & 15;
            ((float4*)hs)[i4] =
                *(const float4*)&h2n[(size_t)k * PIX2 + P0 + p4 * 4];
        }
    } else {
        for (int i4 = tx; i4 < 4096 / 4; i4 += 128) {
            int k = i4 >> 4, p4 = i4 & 15;
            float4 v = make_float4(0.f, 0.f, 0.f, 0.f);
            if (P0 + p4 * 4 + 3 < PIX2)
                v = *(const float4*)&h2n[(size_t)k * PIX2 + P0 + p4 * 4];
            ((float4*)hs)[i4] = v;
        }
    }
    __syncthreads();

    int cg = tx & 15, pg = tx >> 4;
    int c0 = cg * 8, p0 = pg * 8;

    float acc[8][8];
#pragma unroll
    for (int i = 0; i < 8; i++)
#pragma unroll
        for (int j = 0; j < 8; j++) acc[i][j] = 0.f;

#pragma unroll 4
    for (int k = 0; k < C2; k++) {
        float4 ha = *(const float4*)&hs[k * 64 + p0];
        float4 hb = *(const float4*)&hs[k * 64 + p0 + 4];
        float h8[8] = {ha.x, ha.y, ha.z, ha.w, hb.x, hb.y, hb.z, hb.w};
        float4 wa = *(const float4*)&ws[k * C3 + c0];
        float4 wb = *(const float4*)&ws[k * C3 + c0 + 4];
        float w8[8] = {wa.x, wa.y, wa.z, wa.w, wb.x, wb.y, wb.z, wb.w};
#pragma unroll
        for (int i = 0; i < 8; i++)
#pragma unroll
            for (int j = 0; j < 8; j++)
                acc[i][j] += w8[i] * h8[j];
    }

    __syncthreads();                 // done reading hs; reuse it as red[]
    float* red = hs;                 // [128][8]

    bool full = (P0 + 64 <= PIX2);
#pragma unroll
    for (int i = 0; i < 8; i++) {
        float ai = __ldg(&a2[c0 + i]);
        float bi = __ldg(&b2[c0 + i]);
        float s = 0.f;
#pragma unroll
        for (int j = 0; j < 8; j++) {
            float y = fmaxf(acc[i][j] * ai + bi, 0.f);
            if (full || (P0 + p0 + j) < PIX2) s += y;
        }
        red[tx * 8 + i] = s;
    }
    __syncthreads();

    // thread t sums channel t over the 8 pixel groups
    int c = tx;
    int cgr = c >> 3, ii = c & 7;
    float tot = 0.f;
#pragma unroll
    for (int p = 0; p < 8; p++) tot += red[(p * 16 + cgr) * 8 + ii];
    g_part[((size_t)n * NCHUNK + chunk) * C3 + c] = tot;
}

// ---------------------------------------------------------------------------
// GAP reduce
// ---------------------------------------------------------------------------
__global__ void gap_reduce_kernel() {
    int n = blockIdx.x, c = threadIdx.x;
    float s = 0.f;
    for (int ch = 0; ch < NCHUNK; ch++)
        s += g_part[((size_t)n * NCHUNK + ch) * C3 + c];
    g_gap[n * C3 + c] = s * (1.f / (float)PIX2);
}

// ---------------------------------------------------------------------------
// Head GEMV
// ---------------------------------------------------------------------------
__global__ void head_kernel(const float* __restrict__ wh,
                            const float* __restrict__ ah,
                            const float* __restrict__ bh,
                            float* __restrict__ out) {
    __shared__ float gs[C3];
    int n = blockIdx.y;
    if (threadIdx.x < C3) gs[threadIdx.x] = g_gap[n * C3 + threadIdx.x];
    __syncthreads();

    int o = blockIdx.x * blockDim.x + threadIdx.x;
    if (o >= HEADN) return;

    const float* wr = wh + (size_t)o * C3;
    float dot = 0.f;
#pragma unroll 8
    for (int k = 0; k < C3; k++) dot += __ldg(&wr[k]) * gs[k];
    out[(size_t)n * HEADN + o] = fmaxf(dot * __ldg(&ah[o]) + __ldg(&bh[o]), 0.f);
}

// ---------------------------------------------------------------------------
// Launch
// ---------------------------------------------------------------------------
extern "C" void kernel_launch(void* const* d_in, const int* in_sizes, int n_in,
                              void* d_out, int out_size) {
    const float* x      = (const float*)d_in[0];
    const float* w_stem = (const float*)d_in[1];
    const float* a_stem = (const float*)d_in[2];
    const float* b_stem = (const float*)d_in[3];
    const float* w1     = (const float*)d_in[4];
    const float* a1     = (const float*)d_in[5];
    const float* b1     = (const float*)d_in[6];
    const float* w2     = (const float*)d_in[7];
    const float* a2     = (const float*)d_in[8];
    const float* b2     = (const float*)d_in[9];
    const float* w_head = (const float*)d_in[10];
    const float* a_head = (const float*)d_in[11];
    const float* b_head = (const float*)d_in[12];
    float* out = (float*)d_out;

    prep_kernel<<<(288 * C2 + 255) / 256, 256>>>(w_stem, w1, w2);

    conv1_kernel<<<dim3(H1, BN), 128>>>(x, a_stem, b_stem);

    conv2_kernel<<<dim3(H2, BN), 128>>>(a1, b1);

    conv3_gap_kernel<<<dim3(NCHUNK, BN), 128>>>(a2, b2);

    gap_reduce_kernel<<<BN, C3>>>();

    head_kernel<<<dim3((HEADN + 255) / 256, BN), 256>>>(w_head, a_head, b_head, out);
}

// round 6
// speedup vs baseline: 1.5064x; 1.0811x over previous
#include <cuda_runtime.h>
#include <cstdint>
#include <mma.h>

using namespace nvcuda;

// ---------------------------------------------------------------------------
// Shapes
// ---------------------------------------------------------------------------
namespace {
constexpr int BN   = 64;
constexpr int HWIN = 240;
constexpr int H1   = 120;
constexpr int H2   = 60;
constexpr int C0   = 3;
constexpr int C1   = 32;
constexpr int C2   = 64;
constexpr int C3   = 128;
constexpr int HEADN = 1280;
constexpr int PIX2  = H2 * H2;                 // 3600
constexpr int P3    = 64;                      // conv3 px per block
constexpr int NCHUNK = (PIX2 + P3 - 1) / P3;   // 57
constexpr int NTAP = 9;

// conv2 SMEM layout (bytes in dynamic smem)
constexpr int S2_A     = 0;                    // [128 px][32 ci] tf32 = 16 KB
constexpr int S2_B     = 16384;                // [288 k][64 co] tf32 = 72 KB
constexpr int S2_TOTAL = S2_B + 288 * 64 * 4;  // 90112
constexpr int SOUT_LD  = 132;                  // col-major out stage ld (mult 4)
}

// ---------------------------------------------------------------------------
// Scratch
// ---------------------------------------------------------------------------
__device__ float g_h1[(size_t)BN * H1 * H1 * C1];   // channels-last
__device__ float g_h2[(size_t)BN * C2 * PIX2];      // channel-major
__device__ float g_part[BN * NCHUNK * C3];
__device__ float g_gap[BN * C3];
__device__ float g_wst[27 * C1];                    // stem [ci*9+tap][co]
__device__ float g_w2t[C2 * C3];                    // conv3 [k][co]
__device__ float g_w2b[288 * C2];                   // conv2 B [tap*32+ci][co], tf32

__device__ __forceinline__ float f2tf(float x) {
    uint32_t r;
    asm("cvt.rna.tf32.f32 %0, %1;" : "=r"(r) : "f"(x));
    return __uint_as_float(r);
}

// ---------------------------------------------------------------------------
// Prep: stem transpose, conv3 transpose, conv2 B (a1-folded, tf32-rounded)
// ---------------------------------------------------------------------------
__global__ void prep_kernel(const float* __restrict__ wstem,
                            const float* __restrict__ w1,
                            const float* __restrict__ a1,
                            const float* __restrict__ w2) {
    int i = blockIdx.x * blockDim.x + threadIdx.x;
    if (i < 27 * C1) {
        int co = i / 27, kk = i % 27;
        g_wst[kk * C1 + co] = wstem[i];
    }
    if (i < C2 * C3) {
        int k = i / C3, c = i % C3;
        g_w2t[k * C3 + c] = w2[c * C2 + k];
    }
    if (i < C2 * 288) {
        int co = i / 288, r = i % 288;
        int ci = r / 9, tap = r % 9;
        g_w2b[(tap * 32 + ci) * C2 + co] = f2tf(w1[i] * a1[co]);
    }
}

// ---------------------------------------------------------------------------
// Conv1 (stem): 3->32, 3x3 s2 p1, 240^2 -> 120^2, BN + ReLU.
// Output CHANNELS-LAST: g_h1[n][oy][ox][co].
// ---------------------------------------------------------------------------
__global__ __launch_bounds__(128) void conv1_kernel(
        const float* __restrict__ x,
        const float* __restrict__ a,
        const float* __restrict__ b) {
    __shared__ float sO[9][132];
    __shared__ float sE[9][132];
    __shared__ float ws[27 * C1];
    __shared__ float as[C1], bs[C1];

    int oy = blockIdx.x, n = blockIdx.y;
    int tx = threadIdx.x;

    for (int i = tx; i < 27 * C1; i += 128) ws[i] = g_wst[i];
    if (tx < C1) { as[tx] = a[tx]; bs[tx] = b[tx]; }

    const float* xn = x + (size_t)n * C0 * HWIN * HWIN;
    for (int t = tx; t < 2 * 9 * 132; t += 128) {
        int half = t / (9 * 132);
        int rem  = t % (9 * 132);
        int r = rem / 132, j = rem % 132;
        int ky = r / 3, ci = r % 3;
        int iy = oy * 2 - 1 + ky;
        const float* row = xn + ci * HWIN * HWIN + iy * HWIN;
        float v = 0.f;
        if (iy >= 0) {
            if (half == 0) { int sx = 2 * j - 1; if (j <= 120 && sx >= 0) v = row[sx]; }
            else           { if (j <= 119) v = row[2 * j]; }
        }
        if (half == 0) sO[r][j] = v; else sE[r][j] = v;
    }
    __syncthreads();

    int cg = tx & 3, pg = tx >> 2;
    int c0 = cg * 8, ox0 = pg * 4;

    float acc[8][4];
#pragma unroll
    for (int i = 0; i < 8; i++)
#pragma unroll
        for (int j = 0; j < 4; j++) acc[i][j] = 0.f;

#pragma unroll
    for (int ky = 0; ky < 3; ky++) {
#pragma unroll
        for (int ci = 0; ci < 3; ci++) {
            int r = ky * 3 + ci;
            float4 o = *(const float4*)&sO[r][ox0];
            float  o4 = sO[r][ox0 + 4];
            float4 e = *(const float4*)&sE[r][ox0];
#pragma unroll
            for (int kx = 0; kx < 3; kx++) {
                float v0, v1, v2, v3;
                if (kx == 0)      { v0 = o.x; v1 = o.y; v2 = o.z; v3 = o.w; }
                else if (kx == 1) { v0 = e.x; v1 = e.y; v2 = e.z; v3 = e.w; }
                else              { v0 = o.y; v1 = o.z; v2 = o.w; v3 = o4;  }
                const float* wp = &ws[(ci * 9 + ky * 3 + kx) * C1 + c0];
                float4 wa = *(const float4*)wp;
                float4 wb = *(const float4*)(wp + 4);
                float w8[8] = {wa.x, wa.y, wa.z, wa.w, wb.x, wb.y, wb.z, wb.w};
#pragma unroll
                for (int i = 0; i < 8; i++) {
                    acc[i][0] += w8[i] * v0;
                    acc[i][1] += w8[i] * v1;
                    acc[i][2] += w8[i] * v2;
                    acc[i][3] += w8[i] * v3;
                }
            }
        }
    }

    if (pg < 30) {
        float* outp = g_h1 + (((size_t)n * H1 + oy) * H1 + ox0) * C1 + c0;
#pragma unroll
        for (int j = 0; j < 4; j++) {
            float4 lo, hi;
            lo.x = fmaxf(acc[0][j] * as[c0 + 0] + bs[c0 + 0], 0.f);
            lo.y = fmaxf(acc[1][j] * as[c0 + 1] + bs[c0 + 1], 0.f);
            lo.z = fmaxf(acc[2][j] * as[c0 + 2] + bs[c0 + 2], 0.f);
            lo.w = fmaxf(acc[3][j] * as[c0 + 3] + bs[c0 + 3], 0.f);
            hi.x = fmaxf(acc[4][j] * as[c0 + 4] + bs[c0 + 4], 0.f);
            hi.y = fmaxf(acc[5][j] * as[c0 + 5] + bs[c0 + 5], 0.f);
            hi.z = fmaxf(acc[6][j] * as[c0 + 6] + bs[c0 + 6], 0.f);
            hi.w = fmaxf(acc[7][j] * as[c0 + 7] + bs[c0 + 7], 0.f);
            *(float4*)&outp[j * C1]     = lo;
            *(float4*)&outp[j * C1 + 4] = hi;
        }
    }
}

// ---------------------------------------------------------------------------
// Conv2: WMMA tf32 implicit GEMM. 32->64, 3x3 s2 p1, 120^2 -> 60^2.
// CTA = 2 output rows. M=128 px (120 valid), N=64 co, K=288 (9 taps x 32 ci).
// 8 warps in 4M x 2N grid; warp tile 32px x 32co; per-tap A staging.
// a1 folded into B; epilogue adds b1 + ReLU, writes channel-major g_h2.
// ---------------------------------------------------------------------------
__global__ __launch_bounds__(256) void conv2_mma_kernel(
        const float* __restrict__ b1) {
    extern __shared__ char smem[];
    float* sA = (float*)(smem + S2_A);      // [128][32]
    float* sB = (float*)(smem + S2_B);      // [288][64]
    __shared__ float bs[C2];

    int tx = threadIdx.x;
    int wid = tx >> 5;
    int oy0 = blockIdx.x * 2;
    int n = blockIdx.y;

    if (tx < C2) bs[tx] = b1[tx];

    // stage B once (pure copy, already tf32-rounded)
    {
        float4* dst = (float4*)sB;
        const float4* src = (const float4*)g_w2b;
        for (int i = tx; i < 288 * C2 / 4; i += 256) dst[i] = src[i];
    }

    int wm = wid & 3;        // 4 M slices of 32 px
    int wn = wid >> 2;       // 2 N slices of 32 co

    wmma::fragment<wmma::accumulator, 16, 16, 8, float> c[2][2];
#pragma unroll
    for (int i = 0; i < 2; i++)
#pragma unroll
        for (int j = 0; j < 2; j++) wmma::fill_fragment(c[i][j], 0.f);

    const float* h1n = g_h1 + (size_t)n * H1 * H1 * C1;

    for (int tap = 0; tap < NTAP; tap++) {
        int ky = tap / 3, kx = tap % 3;
        __syncthreads();
        // stage A tile [128 px][32 ci] for this tap, tf32-rounded
        for (int it = 0; it < 4; it++) {
            int i = tx + it * 256;          // 1024 float4 items
            int px = i >> 3, c4 = i & 7;
            float4 v = make_float4(0.f, 0.f, 0.f, 0.f);
            if (px < 120) {
                int oy = oy0 + (px >= 60 ? 1 : 0);
                int ox = px >= 60 ? px - 60 : px;
                int iy = oy * 2 - 1 + ky;
                int ix = ox * 2 - 1 + kx;
                if ((unsigned)iy < (unsigned)H1 && (unsigned)ix < (unsigned)H1)
                    v = *(const float4*)&h1n[((size_t)iy * H1 + ix) * C1 + c4 * 4];
            }
            float4 t;
            t.x = f2tf(v.x); t.y = f2tf(v.y); t.z = f2tf(v.z); t.w = f2tf(v.w);
            *(float4*)&sA[px * 32 + c4 * 4] = t;
        }
        __syncthreads();

#pragma unroll
        for (int s = 0; s < 4; s++) {
            wmma::fragment<wmma::matrix_a, 16, 16, 8, wmma::precision::tf32,
                           wmma::row_major> a[2];
            wmma::fragment<wmma::matrix_b, 16, 16, 8, wmma::precision::tf32,
                           wmma::row_major> b[2];
#pragma unroll
            for (int i = 0; i < 2; i++)
                wmma::load_matrix_sync(a[i], &sA[(wm * 32 + i * 16) * 32 + s * 8], 32);
#pragma unroll
            for (int j = 0; j < 2; j++)
                wmma::load_matrix_sync(b[j],
                    &sB[(tap * 32 + s * 8) * C2 + wn * 32 + j * 16], C2);
#pragma unroll
            for (int i = 0; i < 2; i++)
#pragma unroll
                for (int j = 0; j < 2; j++)
                    wmma::mma_sync(c[i][j], a[i], b[j], c[i][j]);
        }
    }

    // epilogue: stage D col-major [co][px] in sB region, then write out
    __syncthreads();
    float* sOut = sB;                        // [64][SOUT_LD], 33.8 KB
#pragma unroll
    for (int i = 0; i < 2; i++)
#pragma unroll
        for (int j = 0; j < 2; j++)
            wmma::store_matrix_sync(
                &sOut[(wn * 32 + j * 16) * SOUT_LD + wm * 32 + i * 16],
                c[i][j], SOUT_LD, wmma::mem_col_major);
    __syncthreads();

    {
        int co = tx >> 2, chunk = tx & 3;
        float bias = bs[co];
        float* o = g_h2 + (size_t)n * C2 * PIX2 + (size_t)co * PIX2 + oy0 * H2;
        const float* src = &sOut[co * SOUT_LD + chunk * 32];
#pragma unroll
        for (int j4 = 0; j4 < 8; j4++) {
            int px = chunk * 32 + j4 * 4;
            if (px >= 120) break;
            float4 y;
            y.x = fmaxf(src[j4 * 4 + 0] + bias, 0.f);
            y.y = fmaxf(src[j4 * 4 + 1] + bias, 0.f);
            y.z = fmaxf(src[j4 * 4 + 2] + bias, 0.f);
            y.w = fmaxf(src[j4 * 4 + 3] + bias, 0.f);
            *(float4*)&o[px] = y;
        }
    }
}

// ---------------------------------------------------------------------------
// Conv3 (1x1, 64->128) + BN + ReLU + partial GAP. (fp32, unchanged)
// ---------------------------------------------------------------------------
__global__ __launch_bounds__(128) void conv3_gap_kernel(
        const float* __restrict__ a2,
        const float* __restrict__ b2) {
    __shared__ float s3[12288];
    float* ws = s3;
    float* hs = s3 + 8192;

    int chunk = blockIdx.x, n = blockIdx.y;
    int tx = threadIdx.x;
    int P0 = chunk * P3;

    for (int i4 = tx; i4 < 8192 / 4; i4 += 128)
        ((float4*)ws)[i4] = ((const float4*)g_w2t)[i4];

    const float* h2n = g_h2 + (size_t)n * C2 * PIX2;
    if (chunk != NCHUNK - 1) {
        for (int i4 = tx; i4 < 4096 / 4; i4 += 128) {
            int k = i4 >> 4, p4 = i4 & 15;
            ((float4*)hs)[i4] =
                *(const float4*)&h2n[(size_t)k * PIX2 + P0 + p4 * 4];
        }
    } else {
        for (int i4 = tx; i4 < 4096 / 4; i4 += 128) {
            int k = i4 >> 4, p4 = i4 & 15;
            float4 v = make_float4(0.f, 0.f, 0.f, 0.f);
            if (P0 + p4 * 4 + 3 < PIX2)
                v = *(const float4*)&h2n[(size_t)k * PIX2 + P0 + p4 * 4];
            ((float4*)hs)[i4] = v;
        }
    }
    __syncthreads();

    int cg = tx & 15, pg = tx >> 4;
    int c0 = cg * 8, p0 = pg * 8;

    float acc[8][8];
#pragma unroll
    for (int i = 0; i < 8; i++)
#pragma unroll
        for (int j = 0; j < 8; j++) acc[i][j] = 0.f;

#pragma unroll 4
    for (int k = 0; k < C2; k++) {
        float4 ha = *(const float4*)&hs[k * 64 + p0];
        float4 hb = *(const float4*)&hs[k * 64 + p0 + 4];
        float h8[8] = {ha.x, ha.y, ha.z, ha.w, hb.x, hb.y, hb.z, hb.w};
        float4 wa = *(const float4*)&ws[k * C3 + c0];
        float4 wb = *(const float4*)&ws[k * C3 + c0 + 4];
        float w8[8] = {wa.x, wa.y, wa.z, wa.w, wb.x, wb.y, wb.z, wb.w};
#pragma unroll
        for (int i = 0; i < 8; i++)
#pragma unroll
            for (int j = 0; j < 8; j++)
                acc[i][j] += w8[i] * h8[j];
    }

    __syncthreads();
    float* red = hs;

    bool full = (P0 + 64 <= PIX2);
#pragma unroll
    for (int i = 0; i < 8; i++) {
        float ai = __ldg(&a2[c0 + i]);
        float bi = __ldg(&b2[c0 + i]);
        float s = 0.f;
#pragma unroll
        for (int j = 0; j < 8; j++) {
            float y = fmaxf(acc[i][j] * ai + bi, 0.f);
            if (full || (P0 + p0 + j) < PIX2) s += y;
        }
        red[tx * 8 + i] = s;
    }
    __syncthreads();

    int c = tx;
    int cgr = c >> 3, ii = c & 7;
    float tot = 0.f;
#pragma unroll
    for (int p = 0; p < 8; p++) tot += red[(p * 16 + cgr) * 8 + ii];
    g_part[((size_t)n * NCHUNK + chunk) * C3 + c] = tot;
}

// ---------------------------------------------------------------------------
// GAP reduce + head GEMV (unchanged)
// ---------------------------------------------------------------------------
__global__ void gap_reduce_kernel() {
    int n = blockIdx.x, c = threadIdx.x;
    float s = 0.f;
    for (int ch = 0; ch < NCHUNK; ch++)
        s += g_part[((size_t)n * NCHUNK + ch) * C3 + c];
    g_gap[n * C3 + c] = s * (1.f / (float)PIX2);
}

__global__ void head_kernel(const float* __restrict__ wh,
                            const float* __restrict__ ah,
                            const float* __restrict__ bh,
                            float* __restrict__ out) {
    __shared__ float gs[C3];
    int n = blockIdx.y;
    if (threadIdx.x < C3) gs[threadIdx.x] = g_gap[n * C3 + threadIdx.x];
    __syncthreads();

    int o = blockIdx.x * blockDim.x + threadIdx.x;
    if (o >= HEADN) return;

    const float* wr = wh + (size_t)o * C3;
    float dot = 0.f;
#pragma unroll 8
    for (int k = 0; k < C3; k++) dot += __ldg(&wr[k]) * gs[k];
    out[(size_t)n * HEADN + o] = fmaxf(dot * __ldg(&ah[o]) + __ldg(&bh[o]), 0.f);
}

// ---------------------------------------------------------------------------
// Launch
// ---------------------------------------------------------------------------
extern "C" void kernel_launch(void* const* d_in, const int* in_sizes, int n_in,
                              void* d_out, int out_size) {
    const float* x      = (const float*)d_in[0];
    const float* w_stem = (const float*)d_in[1];
    const float* a_stem = (const float*)d_in[2];
    const float* b_stem = (const float*)d_in[3];
    const float* w1     = (const float*)d_in[4];
    const float* a1     = (const float*)d_in[5];
    const float* b1     = (const float*)d_in[6];
    const float* w2     = (const float*)d_in[7];
    const float* a2     = (const float*)d_in[8];
    const float* b2     = (const float*)d_in[9];
    const float* w_head = (const float*)d_in[10];
    const float* a_head = (const float*)d_in[11];
    const float* b_head = (const float*)d_in[12];
    float* out = (float*)d_out;

    cudaFuncSetAttribute(conv2_mma_kernel,
                         cudaFuncAttributeMaxDynamicSharedMemorySize, S2_TOTAL);

    prep_kernel<<<(C2 * 288 + 255) / 256, 256>>>(w_stem, w1, a1, w2);

    conv1_kernel<<<dim3(H1, BN), 128>>>(x, a_stem, b_stem);

    conv2_mma_kernel<<<dim3(H2 / 2, BN), 256, S2_TOTAL>>>(b1);

    conv3_gap_kernel<<<dim3(NCHUNK, BN), 128>>>(a2, b2);

    gap_reduce_kernel<<<BN, C3>>>();

    head_kernel<<<dim3((HEADN + 255) / 256, BN), 256>>>(w_head, a_head, b_head, out);
}